// round 15
// baseline (speedup 1.0000x reference)
#include <cuda_runtime.h>
#include <cuda_fp16.h>
#include <mma.h>
#include <cstdint>

using namespace nvcuda;

#define MAXN 500000
#define MAXE 500000
#define F 128

// ---------------- scratch (static device globals; no allocation) ----------------
__device__ __half g_h[(size_t)MAXN * F];    // h = x @ W (fp16)
__device__ __half g_acc[(size_t)MAXN * F];  // edge-sum accumulator (fp16)
__device__ float g_s[MAXN];                 // per-node dot with a_src
__device__ float g_d[MAXN];                 // per-node dot with a_dst
__device__ float g_alpha[MAXE];             // per-edge exp(logit)
__device__ float g_sum;                     // softmax denominator

// ---------------- small helpers ----------------
__device__ __forceinline__ float warpSum(float v) {
    #pragma unroll
    for (int o = 16; o > 0; o >>= 1) v += __shfl_xor_sync(0xFFFFFFFFu, v, o);
    return v;
}

// ---------------- K1: h = x @ W, persistent wmma-fp16, 2 CTAs/SM ----------------
// 256 threads, 8 warps = 4(M) x 2(N); warp tile 32x64 = 2x4 m16n16k16 frags.
// x loaded via LDG.128 -> cvt -> STS fp16; co-resident CTA's MMA hides latency.
// Also zeroes g_acc (fire-and-forget). SMEM: 69632 bytes -> 2 CTAs/SM.
// Epilogue: 8B evict-first stores (g_h is write-once/read-once; keep L2 for g_acc).
#define WH_LD 136
#define XH_LD 136
#define SW_HALFS   (128 * WH_LD)              // 17408
#define XH_HALFS   (128 * XH_LD)              // 17408
#define GSMEM_BYTES (SW_HALFS * 2 + XH_HALFS * 2)

__global__ __launch_bounds__(256, 2) void gemm_mma_kernel(const float* __restrict__ x,
                                                          const float* __restrict__ w,
                                                          int numTiles, int N) {
    extern __shared__ char smem_raw[];
    __half* sW  = reinterpret_cast<__half*>(smem_raw);
    __half* sXh = reinterpret_cast<__half*>(smem_raw + SW_HALFS * 2);
    const int tid = threadIdx.x;
    const int stride = gridDim.x;

    if (blockIdx.x == 0 && tid == 0) g_sum = 0.0f;

    // Zero g_acc: fire-and-forget streaming stores, drain behind compute.
    {
        uint4* a4 = reinterpret_cast<uint4*>(g_acc);
        size_t total = (size_t)N * 16;   // uint4 units (8 halfs each)
        const uint4 z = make_uint4(0u, 0u, 0u, 0u);
        for (size_t i = (size_t)blockIdx.x * 256 + tid; i < total; i += (size_t)stride * 256)
            a4[i] = z;
    }

    // Stage W (K x N row-major) once as fp16.
    #pragma unroll
    for (int i = 0; i < 16; i++) {
        int q = tid + i * 256;       // float4 id, 4096 total
        int k = q >> 5;
        int c4 = q & 31;
        float4 v = reinterpret_cast<const float4*>(w)[q];
        __half2 p0 = __floats2half2_rn(v.x, v.y);
        __half2 p1 = __floats2half2_rn(v.z, v.w);
        uint2 u;
        u.x = *reinterpret_cast<uint32_t*>(&p0);
        u.y = *reinterpret_cast<uint32_t*>(&p1);
        *reinterpret_cast<uint2*>(&sW[k * WH_LD + c4 * 4]) = u;
    }

    const int wid = tid >> 5;
    const int lane = tid & 31;
    const int warp_m = wid & 3;          // 0..3
    const int warp_n = wid >> 2;         // 0..1
    const int n0 = warp_n * 64;

    for (int t = blockIdx.x; t < numTiles; t += stride) {
        __syncthreads();    // prior epilogue readers done; sXh reusable as input tile

        // Load x tile (fp32, coalesced LDG.128), convert, store fp16 to SMEM.
        const float4* src = reinterpret_cast<const float4*>(x + (size_t)t * 128 * F);
        #pragma unroll
        for (int i = 0; i < 16; i++) {
            int q = tid + i * 256;       // float4 id
            int r = q >> 5;
            int c4 = q & 31;
            float4 v = src[q];
            __half2 p0 = __floats2half2_rn(v.x, v.y);
            __half2 p1 = __floats2half2_rn(v.z, v.w);
            uint2 u;
            u.x = *reinterpret_cast<uint32_t*>(&p0);
            u.y = *reinterpret_cast<uint32_t*>(&p1);
            *reinterpret_cast<uint2*>(&sXh[r * XH_LD + c4 * 4]) = u;
        }
        __syncthreads();

        const __half* aBase = sXh + warp_m * 32 * XH_LD;

        wmma::fragment<wmma::accumulator, 16, 16, 16, float> c[2][4];
        #pragma unroll
        for (int mi = 0; mi < 2; mi++)
            #pragma unroll
            for (int ni = 0; ni < 4; ni++) wmma::fill_fragment(c[mi][ni], 0.0f);

        #pragma unroll
        for (int kf = 0; kf < 8; kf++) {
            const int k = kf * 16;
            wmma::fragment<wmma::matrix_a, 16, 16, 16, __half, wmma::row_major> a[2];
            wmma::fragment<wmma::matrix_b, 16, 16, 16, __half, wmma::row_major> b[4];
            #pragma unroll
            for (int mi = 0; mi < 2; mi++)
                wmma::load_matrix_sync(a[mi], aBase + mi * 16 * XH_LD + k, XH_LD);
            #pragma unroll
            for (int ni = 0; ni < 4; ni++)
                wmma::load_matrix_sync(b[ni], &sW[k * WH_LD + n0 + ni * 16], WH_LD);
            #pragma unroll
            for (int mi = 0; mi < 2; mi++)
                #pragma unroll
                for (int ni = 0; ni < 4; ni++)
                    wmma::mma_sync(c[mi][ni], a[mi], b[ni], c[mi][ni]);
        }

        __syncthreads();   // all warps done reading sXh; safe to reuse as staging

        // Epilogue: two 16-row waves through sXh-as-fp32 staging; 8B .cs stores.
        float* myStg = reinterpret_cast<float*>(sXh) + wid * 1024;   // 16x64 fp32
        #pragma unroll
        for (int mi = 0; mi < 2; mi++) {
            #pragma unroll
            for (int ni = 0; ni < 4; ni++)
                wmma::store_matrix_sync(myStg + ni * 16, c[mi][ni], 64, wmma::mem_row_major);
            __syncwarp();
            const size_t m0 = (size_t)t * 128 + warp_m * 32 + mi * 16;
            const float2* stg2 = reinterpret_cast<const float2*>(myStg);
            const int rsub = lane >> 4;          // 0..1
            const int c2 = (lane & 15) * 2;      // float2 index within row (0..30)
            #pragma unroll
            for (int rr = 0; rr < 16; rr += 2) {
                int r = rr + rsub;
                float2 va = stg2[r * 32 + c2];
                float2 vb = stg2[r * 32 + c2 + 1];
                __half2 h0 = __floats2half2_rn(va.x, va.y);
                __half2 h1 = __floats2half2_rn(vb.x, vb.y);
                uint32_t u0 = *reinterpret_cast<uint32_t*>(&h0);
                uint32_t u1 = *reinterpret_cast<uint32_t*>(&h1);
                __half* dst = &g_h[(m0 + r) * F + n0 + (lane & 15) * 4];
                asm volatile("st.global.cs.v2.u32 [%0], {%1,%2};"
                             :: "l"(dst), "r"(u0), "r"(u1) : "memory");
            }
            __syncwarp();
        }
    }
}

// Tail rows [M0, N): one CTA per row, 128 threads (one per output col). fp32 math.
__global__ __launch_bounds__(128) void gemm_tail_kernel(const float* __restrict__ x,
                                                        const float* __restrict__ w,
                                                        int M0, int N) {
    __shared__ float sx[F];
    int r = M0 + blockIdx.x;
    if (r >= N) return;
    sx[threadIdx.x] = x[(size_t)r * F + threadIdx.x];
    __syncthreads();
    float acc = 0.f;
    #pragma unroll 8
    for (int k = 0; k < F; k++) acc = fmaf(sx[k], w[k * F + threadIdx.x], acc);
    g_h[(size_t)r * F + threadIdx.x] = __float2half_rn(acc);
}

// ---------------- K2: acc[row[e]] += h[col[e]]  (fp16 vector atomics) ----------------
__global__ __launch_bounds__(256) void scatter_kernel(const int* __restrict__ ei, int E) {
    int e = (blockIdx.x * blockDim.x + threadIdx.x) >> 5;
    int lane = threadIdx.x & 31;
    if (e >= E) return;
    int r = ei[e];
    int c = ei[E + e];
    uint2 pk = reinterpret_cast<const uint2*>(&g_h[(size_t)c * F])[lane];  // 4 halfs
    __half* dst = &g_acc[(size_t)r * F + lane * 4];
    asm volatile("red.global.add.noftz.v2.f16x2 [%0], {%1,%2};"
                 :: "l"(dst), "r"(pk.x), "r"(pk.y)
                 : "memory");
}

// ---------------- K3: s[i], d[i] from relu(acc+bias) — 8 nodes per warp (ILP) -------
__global__ __launch_bounds__(256) void postproc_kernel(const float* __restrict__ bias,
                                                       const float* __restrict__ att,
                                                       int N) {
    int warp = (blockIdx.x * blockDim.x + threadIdx.x) >> 5;
    int lane = threadIdx.x & 31;
    int nb = warp * 8;
    if (nb >= N) return;
    float4 b  = reinterpret_cast<const float4*>(bias)[lane];
    float4 as = reinterpret_cast<const float4*>(att)[lane];       // a_src
    float4 ad = reinterpret_cast<const float4*>(att)[32 + lane];  // a_dst

    uint2 pk[8];
    #pragma unroll
    for (int j = 0; j < 8; j++) {
        int node = nb + j;
        pk[j] = (node < N) ? reinterpret_cast<const uint2*>(&g_acc[(size_t)node * F])[lane]
                           : make_uint2(0u, 0u);
    }
    float ss[8], dd[8];
    #pragma unroll
    for (int j = 0; j < 8; j++) {
        float2 f0 = __half22float2(*reinterpret_cast<__half2*>(&pk[j].x));
        float2 f1 = __half22float2(*reinterpret_cast<__half2*>(&pk[j].y));
        float vx = fmaxf(f0.x + b.x, 0.f);
        float vy = fmaxf(f0.y + b.y, 0.f);
        float vz = fmaxf(f1.x + b.z, 0.f);
        float vw = fmaxf(f1.y + b.w, 0.f);
        ss[j] = vx * as.x + vy * as.y + vz * as.z + vw * as.w;
        dd[j] = vx * ad.x + vy * ad.y + vz * ad.z + vw * ad.w;
    }
    #pragma unroll
    for (int o = 16; o > 0; o >>= 1) {
        #pragma unroll
        for (int j = 0; j < 8; j++) {
            ss[j] += __shfl_xor_sync(0xFFFFFFFFu, ss[j], o);
            dd[j] += __shfl_xor_sync(0xFFFFFFFFu, dd[j], o);
        }
    }
    if (lane == 0) {
        #pragma unroll
        for (int j = 0; j < 8; j++) {
            if (nb + j < N) { g_s[nb + j] = ss[j]; g_d[nb + j] = dd[j]; }
        }
    }
}

// ---------------- K4: alpha[e]=exp(leaky_relu(s[row]+d[col])); global sum ----------
// Unstable softmax (no max subtraction): logits are small dot products, |logit| << 88,
// so exp cannot overflow; result is mathematically identical to max-shifted softmax.
__global__ __launch_bounds__(256) void alpha_exp_kernel(const int* __restrict__ ei, int E) {
    int e = blockIdx.x * blockDim.x + threadIdx.x;
    int lane = threadIdx.x & 31;
    int wid = threadIdx.x >> 5;
    float ev = 0.f;
    if (e < E) {
        int r = ei[e];
        int c = ei[E + e];
        float v = g_s[r] + g_d[c];
        v = (v > 0.f) ? v : 0.2f * v;
        ev = __expf(v);
        g_alpha[e] = ev;
    }
    __shared__ float ssum[8];
    float s = warpSum(ev);
    if (lane == 0) ssum[wid] = s;
    __syncthreads();
    if (wid == 0) {
        float t = (lane < 8) ? ssum[lane] : 0.f;
        t = warpSum(t);
        if (lane == 0) atomicAdd(&g_sum, t);
    }
}

// ---------------- K5: out[i,:] = relu(acc[i,:]+bias) * alpha[i]/sum ----------------
__global__ __launch_bounds__(256) void scale_kernel(float* __restrict__ out,
                                                    const float* __restrict__ bias,
                                                    int N) {
    size_t i = (size_t)blockIdx.x * blockDim.x + threadIdx.x;  // float4 index
    if (i >= (size_t)N * 32) return;
    int node = (int)(i >> 5);
    float sc = g_alpha[node] / g_sum;
    uint2 pk = reinterpret_cast<const uint2*>(g_acc)[i];
    float2 f0 = __half22float2(*reinterpret_cast<__half2*>(&pk.x));
    float2 f1 = __half22float2(*reinterpret_cast<__half2*>(&pk.y));
    float4 b = reinterpret_cast<const float4*>(bias)[i & 31];
    float4 v;
    v.x = fmaxf(f0.x + b.x, 0.f) * sc;
    v.y = fmaxf(f0.y + b.y, 0.f) * sc;
    v.z = fmaxf(f1.x + b.z, 0.f) * sc;
    v.w = fmaxf(f1.y + b.w, 0.f) * sc;
    reinterpret_cast<float4*>(out)[i] = v;
}

extern "C" void kernel_launch(void* const* d_in, const int* in_sizes, int n_in,
                              void* d_out, int out_size) {
    const float* x   = (const float*)d_in[0];
    const int* ei    = (const int*)d_in[1];     // edge_index: int32
    const float* w   = (const float*)d_in[2];
    const float* att = (const float*)d_in[3];
    const float* bias= (const float*)d_in[4];
    float* out       = (float*)d_out;

    int N = in_sizes[0] / F;   // 500000
    int E = in_sizes[1] / 2;   // 500000

    static int smem_set = 0;
    if (!smem_set) {
        cudaFuncSetAttribute(gemm_mma_kernel, cudaFuncAttributeMaxDynamicSharedMemorySize, GSMEM_BYTES);
        smem_set = 1;
    }

    int fullTiles = N / 128;           // 3906
    int M0 = fullTiles * 128;          // 499968
    int tailRows = N - M0;             // 32
    int gemmGrid = 304;                // 2 CTAs/SM on 152 SMs
    if (gemmGrid > fullTiles) gemmGrid = fullTiles;

    gemm_mma_kernel<<<gemmGrid, 256, GSMEM_BYTES>>>(x, w, fullTiles, N);
    if (tailRows > 0) gemm_tail_kernel<<<tailRows, 128>>>(x, w, M0, N);
    scatter_kernel<<<(E + 7) / 8, 256>>>(ei, E);
    postproc_kernel<<<(int)(((size_t)N / 8 + 7) / 8 + 1), 256>>>(bias, att, N);
    alpha_exp_kernel<<<(E + 255) / 256, 256>>>(ei, E);
    scale_kernel<<<(int)(((size_t)N * 32 + 255) / 256), 256>>>(out, bias, N);
}

// round 16
// speedup vs baseline: 1.0295x; 1.0295x over previous
#include <cuda_runtime.h>
#include <cuda_fp16.h>
#include <mma.h>
#include <cstdint>

using namespace nvcuda;

#define MAXN 500000
#define MAXE 500000
#define F 128

// ---------------- scratch (static device globals; no allocation) ----------------
__device__ __half g_h[(size_t)MAXN * F];    // h = x @ W (fp16)
__device__ __half g_acc[(size_t)MAXN * F];  // edge-sum accumulator (fp16)
__device__ float g_s[MAXN];                 // per-node dot with a_src
__device__ float g_d[MAXN];                 // per-node dot with a_dst
__device__ float g_alpha[MAXE];             // per-edge exp(logit)
__device__ float g_sum;                     // softmax denominator

// ---------------- small helpers ----------------
__device__ __forceinline__ float warpSum(float v) {
    #pragma unroll
    for (int o = 16; o > 0; o >>= 1) v += __shfl_xor_sync(0xFFFFFFFFu, v, o);
    return v;
}

// ---------------- K1: h = x @ W, persistent wmma-fp16, 2 CTAs/SM ----------------
// 256 threads, 8 warps = 4(M) x 2(N); warp tile 32x64 = 2x4 m16n16k16 frags.
// x loaded via LDG.128 -> cvt -> STS fp16; co-resident CTA's MMA hides latency.
// Handles the partial last tile with predicated guards (no separate tail kernel).
// Also zeroes g_acc (fire-and-forget). SMEM: 69632 bytes -> 2 CTAs/SM.
#define WH_LD 136
#define XH_LD 136
#define SW_HALFS   (128 * WH_LD)              // 17408
#define XH_HALFS   (128 * XH_LD)              // 17408
#define GSMEM_BYTES (SW_HALFS * 2 + XH_HALFS * 2)

__global__ __launch_bounds__(256, 2) void gemm_mma_kernel(const float* __restrict__ x,
                                                          const float* __restrict__ w,
                                                          int numTiles, int N) {
    extern __shared__ char smem_raw[];
    __half* sW  = reinterpret_cast<__half*>(smem_raw);
    __half* sXh = reinterpret_cast<__half*>(smem_raw + SW_HALFS * 2);
    const int tid = threadIdx.x;
    const int stride = gridDim.x;

    if (blockIdx.x == 0 && tid == 0) g_sum = 0.0f;

    // Zero g_acc: fire-and-forget streaming stores, drain behind compute.
    {
        uint4* a4 = reinterpret_cast<uint4*>(g_acc);
        size_t total = (size_t)N * 16;   // uint4 units (8 halfs each)
        const uint4 z = make_uint4(0u, 0u, 0u, 0u);
        for (size_t i = (size_t)blockIdx.x * 256 + tid; i < total; i += (size_t)stride * 256)
            a4[i] = z;
    }

    // Stage W (K x N row-major) once as fp16.
    #pragma unroll
    for (int i = 0; i < 16; i++) {
        int q = tid + i * 256;       // float4 id, 4096 total
        int k = q >> 5;
        int c4 = q & 31;
        float4 v = reinterpret_cast<const float4*>(w)[q];
        __half2 p0 = __floats2half2_rn(v.x, v.y);
        __half2 p1 = __floats2half2_rn(v.z, v.w);
        uint2 u;
        u.x = *reinterpret_cast<uint32_t*>(&p0);
        u.y = *reinterpret_cast<uint32_t*>(&p1);
        *reinterpret_cast<uint2*>(&sW[k * WH_LD + c4 * 4]) = u;
    }

    const int wid = tid >> 5;
    const int lane = tid & 31;
    const int warp_m = wid & 3;          // 0..3
    const int warp_n = wid >> 2;         // 0..1
    const int n0 = warp_n * 64;

    for (int t = blockIdx.x; t < numTiles; t += stride) {
        __syncthreads();    // prior epilogue readers done; sXh reusable as input tile

        // Load x tile (fp32, coalesced LDG.128, guarded), convert, store fp16.
        #pragma unroll
        for (int i = 0; i < 16; i++) {
            int q = tid + i * 256;       // float4 id
            int r = q >> 5;
            int c4 = q & 31;
            int grow = t * 128 + r;
            float4 v = make_float4(0.f, 0.f, 0.f, 0.f);
            if (grow < N) v = reinterpret_cast<const float4*>(x)[(size_t)grow * 32 + c4];
            __half2 p0 = __floats2half2_rn(v.x, v.y);
            __half2 p1 = __floats2half2_rn(v.z, v.w);
            uint2 u;
            u.x = *reinterpret_cast<uint32_t*>(&p0);
            u.y = *reinterpret_cast<uint32_t*>(&p1);
            *reinterpret_cast<uint2*>(&sXh[r * XH_LD + c4 * 4]) = u;
        }
        __syncthreads();

        const __half* aBase = sXh + warp_m * 32 * XH_LD;

        wmma::fragment<wmma::accumulator, 16, 16, 16, float> c[2][4];
        #pragma unroll
        for (int mi = 0; mi < 2; mi++)
            #pragma unroll
            for (int ni = 0; ni < 4; ni++) wmma::fill_fragment(c[mi][ni], 0.0f);

        #pragma unroll
        for (int kf = 0; kf < 8; kf++) {
            const int k = kf * 16;
            wmma::fragment<wmma::matrix_a, 16, 16, 16, __half, wmma::row_major> a[2];
            wmma::fragment<wmma::matrix_b, 16, 16, 16, __half, wmma::row_major> b[4];
            #pragma unroll
            for (int mi = 0; mi < 2; mi++)
                wmma::load_matrix_sync(a[mi], aBase + mi * 16 * XH_LD + k, XH_LD);
            #pragma unroll
            for (int ni = 0; ni < 4; ni++)
                wmma::load_matrix_sync(b[ni], &sW[k * WH_LD + n0 + ni * 16], WH_LD);
            #pragma unroll
            for (int mi = 0; mi < 2; mi++)
                #pragma unroll
                for (int ni = 0; ni < 4; ni++)
                    wmma::mma_sync(c[mi][ni], a[mi], b[ni], c[mi][ni]);
        }

        __syncthreads();   // all warps done reading sXh; safe to reuse as staging

        // Epilogue: two 16-row waves through sXh-as-fp32 staging; 8B stores (guarded).
        float* myStg = reinterpret_cast<float*>(sXh) + wid * 1024;   // 16x64 fp32
        #pragma unroll
        for (int mi = 0; mi < 2; mi++) {
            #pragma unroll
            for (int ni = 0; ni < 4; ni++)
                wmma::store_matrix_sync(myStg + ni * 16, c[mi][ni], 64, wmma::mem_row_major);
            __syncwarp();
            const size_t m0 = (size_t)t * 128 + warp_m * 32 + mi * 16;
            const float2* stg2 = reinterpret_cast<const float2*>(myStg);
            const int rsub = lane >> 4;          // 0..1
            const int c2 = (lane & 15) * 2;      // float2 index within row
            #pragma unroll
            for (int rr = 0; rr < 16; rr += 2) {
                int r = rr + rsub;
                size_t grow = m0 + r;
                if (grow < (size_t)N) {
                    float2 va = stg2[r * 32 + c2];
                    float2 vb = stg2[r * 32 + c2 + 1];
                    __half2 h0 = __floats2half2_rn(va.x, va.y);
                    __half2 h1 = __floats2half2_rn(vb.x, vb.y);
                    uint2 u;
                    u.x = *reinterpret_cast<uint32_t*>(&h0);
                    u.y = *reinterpret_cast<uint32_t*>(&h1);
                    *reinterpret_cast<uint2*>(&g_h[grow * F + n0 + (lane & 15) * 4]) = u;
                }
            }
            __syncwarp();
        }
    }
}

// ---------------- K2: acc[row[e]] += h[col[e]]  (fp16 vector atomics) ----------------
__global__ __launch_bounds__(256) void scatter_kernel(const int* __restrict__ ei, int E) {
    int e = (blockIdx.x * blockDim.x + threadIdx.x) >> 5;
    int lane = threadIdx.x & 31;
    if (e >= E) return;
    int r = ei[e];
    int c = ei[E + e];
    uint2 pk = reinterpret_cast<const uint2*>(&g_h[(size_t)c * F])[lane];  // 4 halfs
    __half* dst = &g_acc[(size_t)r * F + lane * 4];
    asm volatile("red.global.add.noftz.v2.f16x2 [%0], {%1,%2};"
                 :: "l"(dst), "r"(pk.x), "r"(pk.y)
                 : "memory");
}

// ---------------- K3: s[i], d[i] from relu(acc+bias) — 8 nodes per warp (ILP) -------
__global__ __launch_bounds__(256) void postproc_kernel(const float* __restrict__ bias,
                                                       const float* __restrict__ att,
                                                       int N) {
    int warp = (blockIdx.x * blockDim.x + threadIdx.x) >> 5;
    int lane = threadIdx.x & 31;
    int nb = warp * 8;
    if (nb >= N) return;
    float4 b  = reinterpret_cast<const float4*>(bias)[lane];
    float4 as = reinterpret_cast<const float4*>(att)[lane];       // a_src
    float4 ad = reinterpret_cast<const float4*>(att)[32 + lane];  // a_dst

    uint2 pk[8];
    #pragma unroll
    for (int j = 0; j < 8; j++) {
        int node = nb + j;
        pk[j] = (node < N) ? reinterpret_cast<const uint2*>(&g_acc[(size_t)node * F])[lane]
                           : make_uint2(0u, 0u);
    }
    float ss[8], dd[8];
    #pragma unroll
    for (int j = 0; j < 8; j++) {
        float2 f0 = __half22float2(*reinterpret_cast<__half2*>(&pk[j].x));
        float2 f1 = __half22float2(*reinterpret_cast<__half2*>(&pk[j].y));
        float vx = fmaxf(f0.x + b.x, 0.f);
        float vy = fmaxf(f0.y + b.y, 0.f);
        float vz = fmaxf(f1.x + b.z, 0.f);
        float vw = fmaxf(f1.y + b.w, 0.f);
        ss[j] = vx * as.x + vy * as.y + vz * as.z + vw * as.w;
        dd[j] = vx * ad.x + vy * ad.y + vz * ad.z + vw * ad.w;
    }
    #pragma unroll
    for (int o = 16; o > 0; o >>= 1) {
        #pragma unroll
        for (int j = 0; j < 8; j++) {
            ss[j] += __shfl_xor_sync(0xFFFFFFFFu, ss[j], o);
            dd[j] += __shfl_xor_sync(0xFFFFFFFFu, dd[j], o);
        }
    }
    if (lane == 0) {
        #pragma unroll
        for (int j = 0; j < 8; j++) {
            if (nb + j < N) { g_s[nb + j] = ss[j]; g_d[nb + j] = dd[j]; }
        }
    }
}

// ---------------- K4: alpha[e]=exp(leaky_relu(s[row]+d[col])); 2 edges/thread -------
// Unstable softmax (no max subtraction): logits are small dot products, |logit| << 88,
// so exp cannot overflow; result is mathematically identical to max-shifted softmax.
__global__ __launch_bounds__(256) void alpha_exp_kernel(const int* __restrict__ ei, int E) {
    int e0 = (blockIdx.x * blockDim.x + threadIdx.x) * 2;
    int lane = threadIdx.x & 31;
    int wid = threadIdx.x >> 5;
    float ev0 = 0.f, ev1 = 0.f;
    if (e0 < E) {
        int r0 = ei[e0];
        int c0 = ei[E + e0];
        int r1 = 0, c1 = 0;
        bool has1 = (e0 + 1) < E;
        if (has1) { r1 = ei[e0 + 1]; c1 = ei[E + e0 + 1]; }
        float s0 = g_s[r0], d0 = g_d[c0];
        float s1 = has1 ? g_s[r1] : 0.f;
        float d1 = has1 ? g_d[c1] : 0.f;
        float v0 = s0 + d0;
        float v1 = s1 + d1;
        v0 = (v0 > 0.f) ? v0 : 0.2f * v0;
        v1 = (v1 > 0.f) ? v1 : 0.2f * v1;
        ev0 = __expf(v0);
        ev1 = has1 ? __expf(v1) : 0.f;
        if (has1) {
            float2 st = make_float2(ev0, ev1);
            *reinterpret_cast<float2*>(&g_alpha[e0]) = st;
        } else {
            g_alpha[e0] = ev0;
        }
    }
    __shared__ float ssum[8];
    float s = warpSum(ev0 + ev1);
    if (lane == 0) ssum[wid] = s;
    __syncthreads();
    if (wid == 0) {
        float t = (lane < 8) ? ssum[lane] : 0.f;
        t = warpSum(t);
        if (lane == 0) atomicAdd(&g_sum, t);
    }
}

// ---------------- K5: out[i,:] = relu(acc[i,:]+bias) * alpha[i]/sum ----------------
__global__ __launch_bounds__(256) void scale_kernel(float* __restrict__ out,
                                                    const float* __restrict__ bias,
                                                    int N) {
    size_t i = (size_t)blockIdx.x * blockDim.x + threadIdx.x;  // float4 index
    if (i >= (size_t)N * 32) return;
    int node = (int)(i >> 5);
    float sc = g_alpha[node] / g_sum;
    uint2 pk = reinterpret_cast<const uint2*>(g_acc)[i];
    float2 f0 = __half22float2(*reinterpret_cast<__half2*>(&pk.x));
    float2 f1 = __half22float2(*reinterpret_cast<__half2*>(&pk.y));
    float4 b = reinterpret_cast<const float4*>(bias)[i & 31];
    float4 v;
    v.x = fmaxf(f0.x + b.x, 0.f) * sc;
    v.y = fmaxf(f0.y + b.y, 0.f) * sc;
    v.z = fmaxf(f1.x + b.z, 0.f) * sc;
    v.w = fmaxf(f1.y + b.w, 0.f) * sc;
    reinterpret_cast<float4*>(out)[i] = v;
}

extern "C" void kernel_launch(void* const* d_in, const int* in_sizes, int n_in,
                              void* d_out, int out_size) {
    const float* x   = (const float*)d_in[0];
    const int* ei    = (const int*)d_in[1];     // edge_index: int32
    const float* w   = (const float*)d_in[2];
    const float* att = (const float*)d_in[3];
    const float* bias= (const float*)d_in[4];
    float* out       = (float*)d_out;

    int N = in_sizes[0] / F;   // 500000
    int E = in_sizes[1] / 2;   // 500000

    static int smem_set = 0;
    if (!smem_set) {
        cudaFuncSetAttribute(gemm_mma_kernel, cudaFuncAttributeMaxDynamicSharedMemorySize, GSMEM_BYTES);
        smem_set = 1;
    }

    int numTiles = (N + 127) / 128;    // 3907 (last tile partial, guarded)
    int gemmGrid = 304;                // 2 CTAs/SM on 152 SMs
    if (gemmGrid > numTiles) gemmGrid = numTiles;

    gemm_mma_kernel<<<gemmGrid, 256, GSMEM_BYTES>>>(x, w, numTiles, N);
    scatter_kernel<<<(E + 7) / 8, 256>>>(ei, E);
    postproc_kernel<<<(int)(((size_t)N / 8 + 7) / 8 + 1), 256>>>(bias, att, N);
    alpha_exp_kernel<<<((E + 1) / 2 + 255) / 256, 256>>>(ei, E);
    scale_kernel<<<(int)(((size_t)N * 32 + 255) / 256), 256>>>(out, bias, N);
}